// round 16
// baseline (speedup 1.0000x reference)
#include <cuda_runtime.h>
#include <cuda_fp16.h>
#include <math.h>
#include <stdint.h>

#define BB 16
#define CC 256
#define LL 2048
#define EPS 1e-5f

// ======================= helpers =======================
__device__ __forceinline__ uint32_t smem_to_u32(const void* p) {
    uint32_t a;
    asm("{ .reg .u64 t; cvta.to.shared.u64 t, %1; cvt.u32.u64 %0, t; }" : "=r"(a) : "l"(p));
    return a;
}
__device__ __forceinline__ void cp_async16(uint32_t s, const void* g) {
    asm volatile("cp.async.cg.shared.global [%0], [%1], 16;" :: "r"(s), "l"(g));
}
#define CP_COMMIT() asm volatile("cp.async.commit_group;" ::: "memory")
#define CP_WAIT(n)  asm volatile("cp.async.wait_group %0;" :: "n"(n) : "memory")

__device__ __forceinline__ void ldsm4(uint32_t* r, uint32_t a) {
    asm volatile("ldmatrix.sync.aligned.m8n8.x4.shared.b16 {%0,%1,%2,%3}, [%4];"
                 : "=r"(r[0]), "=r"(r[1]), "=r"(r[2]), "=r"(r[3]) : "r"(a));
}
__device__ __forceinline__ void mma16816(float* c, const uint32_t* a, uint32_t b0, uint32_t b1) {
    asm volatile("mma.sync.aligned.m16n8k16.row.col.f32.f16.f16.f32 "
                 "{%0,%1,%2,%3}, {%4,%5,%6,%7}, {%8,%9}, {%0,%1,%2,%3};"
                 : "+f"(c[0]), "+f"(c[1]), "+f"(c[2]), "+f"(c[3])
                 : "r"(a[0]), "r"(a[1]), "r"(a[2]), "r"(a[3]), "r"(b0), "r"(b1));
}
__device__ __forceinline__ uint32_t pack_h2(__half a, __half b) {
    __half2 t = __halves2half2(a, b);
    return *reinterpret_cast<uint32_t*>(&t);
}

// ======================= scratch =======================
#define NLC  ((size_t)BB * LL * CC)
#define NLLs ((size_t)BB * LL * LL)

__device__ __align__(256) __half d_xT_hi[NLC], d_xT_lo[NLC];       // x^T (B,L,C)
__device__ __align__(256) __half d_Mt_hi[CC * CC], d_Mt_lo[CC * CC]; // Wp^T Wt
__device__ __align__(256) __half d_Nt_hi[CC * CC], d_Nt_lo[CC * CC]; // Ww Wg
__device__ float d_qv[CC], d_rv[CC];                                // Wp^T bt ; Ww bg
__device__ __align__(256) __half d_kT_hi[NLC], d_kT_lo[NLC];       // kappa^T (B,L,C)
__device__ __align__(256) __half d_e_hi[NLC];                      // eta (B,C,L) hi only
__device__ __align__(256) float  d_f[NLLs];                        // logits (B,L,L)
__device__ __align__(256) __half d_P[NLLs];                        // softmax fp16
__device__ __align__(256) __half d_wy_h[NLC];                      // W_y fp16 (B,C,L)
__device__ float d_psum[CC], d_psq[CC];
__device__ float d_mean[CC], d_rstd[CC];

// ======================= prep kernels =======================
__global__ __launch_bounds__(256)
void transpose_split_kernel(const float* __restrict__ src,
                            __half* __restrict__ dhi, __half* __restrict__ dlo,
                            int R, int S)
{
    __shared__ float tile[32][33];
    const size_t bo = (size_t)R * S * blockIdx.z;
    const int s0 = blockIdx.x * 32, r0 = blockIdx.y * 32;
    const int tx = threadIdx.x, ty = threadIdx.y;
#pragma unroll
    for (int k = 0; k < 4; k++)
        tile[ty + 8 * k][tx] = src[bo + (size_t)(r0 + ty + 8 * k) * S + s0 + tx];
    __syncthreads();
#pragma unroll
    for (int k = 0; k < 4; k++) {
        float v = tile[tx][ty + 8 * k];
        __half h = __float2half(v);
        size_t di = bo + (size_t)(s0 + ty + 8 * k) * R + r0 + tx;
        dhi[di] = h;
        dlo[di] = __float2half(v - __half2float(h));
    }
}

__global__ __launch_bounds__(256)
void wprep_kernel(const float* __restrict__ Wt, const float* __restrict__ bt,
                  const float* __restrict__ Wp,
                  const float* __restrict__ Wg, const float* __restrict__ bg,
                  const float* __restrict__ Ww,
                  __half* __restrict__ Mhi, __half* __restrict__ Mlo, float* __restrict__ qv,
                  __half* __restrict__ Nhi, __half* __restrict__ Nlo, float* __restrict__ rv)
{
    const int c = blockIdx.x, k = threadIdx.x;
    if (blockIdx.y == 0) {
        float acc = 0.f;
        for (int j = 0; j < CC; j++) acc += Wp[j * CC + c] * Wt[j * CC + k];
        __half h = __float2half(acc);
        Mhi[c * CC + k] = h;
        Mlo[c * CC + k] = __float2half(acc - __half2float(h));
        if (k == 0) {
            float q = 0.f;
            for (int j = 0; j < CC; j++) q += Wp[j * CC + c] * bt[j];
            qv[c] = q;
        }
    } else {
        float acc = 0.f;
        for (int j = 0; j < CC; j++) acc += Ww[c * CC + j] * Wg[j * CC + k];
        __half h = __float2half(acc);
        Nhi[c * CC + k] = h;
        Nlo[c * CC + k] = __float2half(acc - __half2float(h));
        if (k == 0) {
            float r = 0.f;
            for (int j = 0; j < CC; j++) r += Ww[c * CC + j] * bg[j];
            rv[c] = r;
        }
    }
}

__global__ void bn_zero_kernel(float* __restrict__ psum, float* __restrict__ psq)
{
    psum[threadIdx.x] = 0.f;
    psq[threadIdx.x]  = 0.f;
}

// ======================= merged split-fp16 mma.sync GEMM body =======================
// 256-thread CTA, 8 warps (2x4), warp tile 64x32, CTA tile 128x128. 2 CTAs/SM.
// MODE 1 (2-stage): KC "hi" chunks {Ahi,Bhi,Blo}: acc += Ahi*Bhi + Ahi*Blo;
//         then KC "lo" chunks {Alo,Bhi}: acc += Alo*Bhi.  (3-pass)
// MODE 2 (2-stage): KC "hi" chunks only: acc += Ahi*Bhi + Ahi*Blo.  (2-pass)
// MODE 0 (3-stage): KC chunks, Ahi*Bhi only.  (1-pass)
// EPI: 0 = fp32 out, 1 = split fp16 hi+lo out, 2 = fp16 hi out.
// BNRED: 0 none, 1 per-column stats, 2 per-row stats.
#define GBM 128
#define GBN 128
#define GBK 64

template<int MODE, int BNRED>
__device__ __forceinline__ void gemm_body(
    const __half* __restrict__ Ahi, const __half* __restrict__ Alo,
    const __half* __restrict__ Bhi, const __half* __restrict__ Blo,
    const float* __restrict__ bias, int BIASROW, int EPI,
    float* __restrict__ Cf, __half* __restrict__ Chi, __half* __restrict__ Clo,
    float* __restrict__ gpsum, float* __restrict__ gpsq,
    int K, int lda, int ldb, int ldc,
    int mBase, int nBase, size_t aoff, size_t boff, size_t coff,
    char* smem)
{
    constexpr uint32_t STG  = MODE ? 49152u : 32768u;
    constexpr int      NSTG = MODE ? 2 : 3;
    const uint32_t sbase = smem_to_u32(smem);

    const int tid  = threadIdx.x;
    const int lane = tid & 31;
    const int wid  = tid >> 5;
    const int wm   = wid >> 2;
    const int wn   = wid & 3;

    const int KC = K / GBK;
    const int NCH = (MODE == 1) ? 2 * KC : KC;

    float acc[4][4][4];
#pragma unroll
    for (int i = 0; i < 4; i++)
#pragma unroll
        for (int j = 0; j < 4; j++)
#pragma unroll
            for (int q = 0; q < 4; q++) acc[i][j][q] = 0.f;

    auto issue_chunk = [&](int ch) {
        const bool hi = (ch < KC) || (MODE != 1);
        const int koff = ((MODE == 1 && ch >= KC) ? ch - KC : ch) * GBK;
        const __half* pa = (hi ? Ahi : Alo) + aoff;
        const uint32_t Ab = sbase + (uint32_t)(ch % NSTG) * STG;
        const uint32_t B0 = Ab + 16384;
#pragma unroll
        for (int i = 0; i < 4; i++) {
            int idx = tid + i * 256;
            int r = idx >> 3, c = idx & 7;
            uint32_t d = Ab + r * 128 + ((c ^ (r & 7)) << 4);
            cp_async16(d, pa + (size_t)(mBase + r) * lda + koff + c * 8);
        }
#pragma unroll
        for (int i = 0; i < 4; i++) {
            int idx = tid + i * 256;
            int r = idx >> 3, c = idx & 7;
            uint32_t d = B0 + r * 128 + ((c ^ (r & 7)) << 4);
            cp_async16(d, Bhi + boff + (size_t)(nBase + r) * ldb + koff + c * 8);
        }
        if (MODE && hi) {
            const uint32_t B1 = Ab + 32768;
#pragma unroll
            for (int i = 0; i < 4; i++) {
                int idx = tid + i * 256;
                int r = idx >> 3, c = idx & 7;
                uint32_t d = B1 + r * 128 + ((c ^ (r & 7)) << 4);
                cp_async16(d, Blo + boff + (size_t)(nBase + r) * ldb + koff + c * 8);
            }
        }
    };

    issue_chunk(0); CP_COMMIT();
    if (MODE == 0 && NCH > 1) { issue_chunk(1); CP_COMMIT(); }

    const int laA = lane & 15;
    const int lcA = lane >> 4;
    const int lrB = ((lane >> 4) << 3) + (lane & 7);
    const int lcB = (lane >> 3) & 1;

    for (int ch = 0; ch < NCH; ch++) {
        if (MODE == 0) {
            if (ch + 1 < NCH) { CP_WAIT(1); } else { CP_WAIT(0); }
        } else {
            CP_WAIT(0);
        }
        __syncthreads();
        {
            const int next = (MODE == 0) ? ch + 2 : ch + 1;
            if (next < NCH) { issue_chunk(next); CP_COMMIT(); }
        }

        const bool two = MODE && ((MODE == 2) || (ch < KC));
        const uint32_t Ab = sbase + (uint32_t)(ch % NSTG) * STG;
        const uint32_t B0 = Ab + 16384;
        const uint32_t B1 = Ab + 32768;

#pragma unroll
        for (int ks = 0; ks < 4; ks++) {
            uint32_t afr[4][4], bh[2][4], bl[2][4];
#pragma unroll
            for (int i = 0; i < 4; i++) {
                int row = wm * 64 + i * 16 + laA;
                int chk = ks * 2 + lcA;
                ldsm4(afr[i], Ab + row * 128 + ((chk ^ (row & 7)) << 4));
            }
#pragma unroll
            for (int j = 0; j < 2; j++) {
                int row = wn * 32 + j * 16 + lrB;
                int chk = ks * 2 + lcB;
                ldsm4(bh[j], B0 + row * 128 + ((chk ^ (row & 7)) << 4));
            }
            if (two) {
#pragma unroll
                for (int j = 0; j < 2; j++) {
                    int row = wn * 32 + j * 16 + lrB;
                    int chk = ks * 2 + lcB;
                    ldsm4(bl[j], B1 + row * 128 + ((chk ^ (row & 7)) << 4));
                }
            }
#pragma unroll
            for (int i = 0; i < 4; i++)
#pragma unroll
                for (int j = 0; j < 4; j++)
                    mma16816(acc[i][j], afr[i], bh[j >> 1][(j & 1) * 2],
                             bh[j >> 1][(j & 1) * 2 + 1]);
            if (two) {
#pragma unroll
                for (int i = 0; i < 4; i++)
#pragma unroll
                    for (int j = 0; j < 4; j++)
                        mma16816(acc[i][j], afr[i], bl[j >> 1][(j & 1) * 2],
                                 bl[j >> 1][(j & 1) * 2 + 1]);
            }
        }
    }

    // ---- epilogue ----
    float* bnS = (float*)smem;
    float* bnQ = (float*)smem + 128;
    if (BNRED) {
        __syncthreads();
        if (tid < 128) { bnS[tid] = 0.f; bnQ[tid] = 0.f; }
        __syncthreads();
    }
    float lsum[8], lsq[8];
    if (BNRED) {
#pragma unroll
        for (int t = 0; t < 8; t++) { lsum[t] = 0.f; lsq[t] = 0.f; }
    }

    const int g  = lane >> 2;
    const int tg = lane & 3;
#pragma unroll
    for (int i = 0; i < 4; i++) {
        const int rm0 = mBase + wm * 64 + i * 16 + g;
        const int rm1 = rm0 + 8;
        float rb0 = 0.f, rb1 = 0.f;
        if (BIASROW && bias) { rb0 = bias[rm0]; rb1 = bias[rm1]; }
#pragma unroll
        for (int j = 0; j < 4; j++) {
            const int cn = nBase + wn * 32 + j * 8 + tg * 2;
            float c0 = acc[i][j][0], c1 = acc[i][j][1];
            float c2 = acc[i][j][2], c3 = acc[i][j][3];
            if (bias) {
                if (BIASROW) { c0 += rb0; c1 += rb0; c2 += rb1; c3 += rb1; }
                else {
                    float b0 = bias[cn], b1 = bias[cn + 1];
                    c0 += b0; c1 += b1; c2 += b0; c3 += b1;
                }
            }
            if (BNRED == 1) {
                lsum[j * 2]     += c0 + c2;
                lsq [j * 2]     += c0 * c0 + c2 * c2;
                lsum[j * 2 + 1] += c1 + c3;
                lsq [j * 2 + 1] += c1 * c1 + c3 * c3;
            } else if (BNRED == 2) {
                lsum[i * 2]     += c0 + c1;
                lsq [i * 2]     += c0 * c0 + c1 * c1;
                lsum[i * 2 + 1] += c2 + c3;
                lsq [i * 2 + 1] += c2 * c2 + c3 * c3;
            }
            const size_t o0 = coff + (size_t)rm0 * ldc + cn;
            const size_t o1 = coff + (size_t)rm1 * ldc + cn;
            if (EPI == 0) {
                *(float2*)(Cf + o0) = make_float2(c0, c1);
                *(float2*)(Cf + o1) = make_float2(c2, c3);
            } else {
                __half h0 = __float2half(c0), h1 = __float2half(c1);
                __half h2 = __float2half(c2), h3 = __float2half(c3);
                *(uint32_t*)(Chi + o0) = pack_h2(h0, h1);
                *(uint32_t*)(Chi + o1) = pack_h2(h2, h3);
                if (EPI == 1) {
                    __half l0 = __float2half(c0 - __half2float(h0));
                    __half l1 = __float2half(c1 - __half2float(h1));
                    __half l2 = __float2half(c2 - __half2float(h2));
                    __half l3 = __float2half(c3 - __half2float(h3));
                    *(uint32_t*)(Clo + o0) = pack_h2(l0, l1);
                    *(uint32_t*)(Clo + o1) = pack_h2(l2, l3);
                }
            }
        }
    }

    if (BNRED == 1) {
#pragma unroll
        for (int j = 0; j < 4; j++) {
#pragma unroll
            for (int h = 0; h < 2; h++) {
                int lc = wn * 32 + j * 8 + tg * 2 + h;
                atomicAdd(&bnS[lc], lsum[j * 2 + h]);
                atomicAdd(&bnQ[lc], lsq[j * 2 + h]);
            }
        }
        __syncthreads();
        if (tid < 128) {
            atomicAdd(&gpsum[nBase + tid], bnS[tid]);
            atomicAdd(&gpsq[nBase + tid],  bnQ[tid]);
        }
    } else if (BNRED == 2) {
#pragma unroll
        for (int i = 0; i < 4; i++) {
#pragma unroll
            for (int h = 0; h < 2; h++) {
                int lr = wm * 64 + i * 16 + h * 8 + g;
                atomicAdd(&bnS[lr], lsum[i * 2 + h]);
                atomicAdd(&bnQ[lr], lsq[i * 2 + h]);
            }
        }
        __syncthreads();
        if (tid < 128) {
            atomicAdd(&gpsum[mBase + tid], bnS[tid]);
            atomicAdd(&gpsq[mBase + tid],  bnQ[tid]);
        }
    }
}

// ---- merged G1+G2 launch: 1024 CTAs ----
__global__ __launch_bounds__(256, 2)
void g12_kernel(const __half* __restrict__ xT_hi, const __half* __restrict__ xT_lo,
                const __half* __restrict__ Mt_hi, const __half* __restrict__ Mt_lo,
                const __half* __restrict__ Nt_hi, const __half* __restrict__ Nt_lo,
                const float* __restrict__ qv, const float* __restrict__ rv,
                __half* __restrict__ kT_hi, __half* __restrict__ kT_lo,
                __half* __restrict__ e_hi)
{
    extern __shared__ char smem[];
    const size_t sLC = (size_t)LL * CC;
    const int id = blockIdx.x;
    if (id < 512) {
        const int bx = id & 1, by = (id >> 1) & 15, bz = id >> 5;
        gemm_body<1, 0>(xT_hi, xT_lo, Mt_hi, Mt_lo, qv, /*BIASROW=*/0, /*EPI=*/1,
                        nullptr, kT_hi, kT_lo, nullptr, nullptr,
                        CC, CC, CC, CC,
                        by * GBM, bx * GBN, (size_t)bz * sLC, 0, (size_t)bz * sLC,
                        smem);
    } else {
        const int id2 = id - 512;
        const int bx = id2 & 15, by = (id2 >> 4) & 1, bz = id2 >> 5;
        gemm_body<1, 0>(Nt_hi, Nt_lo, xT_hi, xT_lo, rv, /*BIASROW=*/1, /*EPI=*/2,
                        nullptr, e_hi, nullptr, nullptr, nullptr,
                        CC, CC, CC, LL,
                        by * GBM, bx * GBN, 0, (size_t)bz * sLC, (size_t)bz * sLC,
                        smem);
    }
}

// ---- G3 (2-pass): f[l,m] = sum_c kappaT_hi[l,c]*(xT_hi+xT_lo)[m,c] ----
__global__ __launch_bounds__(256, 2)
void g3_kernel(const __half* __restrict__ kT_hi, const __half* __restrict__ kT_lo,
               const __half* __restrict__ xT_hi, const __half* __restrict__ xT_lo,
               float* __restrict__ f, int zBase)
{
    extern __shared__ char smem[];
    const size_t sLC = (size_t)LL * CC;
    const size_t sLL = (size_t)LL * LL;
    const int bz = zBase + blockIdx.z;
    gemm_body<2, 0>(kT_hi, kT_lo, xT_hi, xT_lo, nullptr, 0, /*EPI=*/0,
                    f, nullptr, nullptr, nullptr, nullptr,
                    CC, CC, CC, LL,
                    blockIdx.y * GBM, blockIdx.x * GBN,
                    (size_t)bz * sLC, (size_t)bz * sLC,
                    (size_t)bz * sLL, smem);
}

// ---- G4: wy_h[c,l] = fp16( sum_m e_hi[c,m] P[l,m] + bw[c] ), per-channel stats ----
__global__ __launch_bounds__(256, 2)
void g4_kernel(const __half* __restrict__ e_hi, const __half* __restrict__ P,
               const float* __restrict__ bw, __half* __restrict__ wy_h,
               float* __restrict__ psum, float* __restrict__ psq, int zBase)
{
    extern __shared__ char smem[];
    const size_t sLC = (size_t)LL * CC;
    const size_t sLL = (size_t)LL * LL;
    const int bz = zBase + blockIdx.z;
    gemm_body<0, 2>(e_hi, nullptr, P, nullptr, bw, /*BIASROW=*/1, /*EPI=*/2,
                    nullptr, wy_h, nullptr, psum, psq,
                    LL, LL, LL, LL,
                    blockIdx.y * GBM, blockIdx.x * GBN,
                    (size_t)bz * sLC, (size_t)bz * sLL,
                    (size_t)bz * sLC, smem);
}

// ======================= softmax: fp32 logits -> fp16 P =======================
__global__ __launch_bounds__(256)
void softmax_kernel(const float* __restrict__ f, __half* __restrict__ P)
{
    __shared__ float red[8];
    const float4* F4 = (const float4*)(f + (size_t)blockIdx.x * LL);
    uint2* P4 = (uint2*)(P + (size_t)blockIdx.x * LL);
    const int tid = threadIdx.x;

    float4 q0 = F4[tid], q1 = F4[256 + tid];
    float v[8] = {q0.x, q0.y, q0.z, q0.w, q1.x, q1.y, q1.z, q1.w};
    float m = -INFINITY;
#pragma unroll
    for (int j = 0; j < 8; j++) m = fmaxf(m, v[j]);
#pragma unroll
    for (int o = 16; o; o >>= 1) m = fmaxf(m, __shfl_xor_sync(0xffffffffu, m, o));
    if ((tid & 31) == 0) red[tid >> 5] = m;
    __syncthreads();
    float bm = red[0];
#pragma unroll
    for (int w = 1; w < 8; w++) bm = fmaxf(bm, red[w]);
    float s = 0.f;
#pragma unroll
    for (int j = 0; j < 8; j++) { v[j] = __expf(v[j] - bm); s += v[j]; }
#pragma unroll
    for (int o = 16; o; o >>= 1) s += __shfl_xor_sync(0xffffffffu, s, o);
    __syncthreads();
    if ((tid & 31) == 0) red[tid >> 5] = s;
    __syncthreads();
    float bs = 0.f;
#pragma unroll
    for (int w = 0; w < 8; w++) bs += red[w];
    const float inv = 1.f / bs;
    uint2 o0, o1;
    o0.x = pack_h2(__float2half(v[0] * inv), __float2half(v[1] * inv));
    o0.y = pack_h2(__float2half(v[2] * inv), __float2half(v[3] * inv));
    o1.x = pack_h2(__float2half(v[4] * inv), __float2half(v[5] * inv));
    o1.y = pack_h2(__float2half(v[6] * inv), __float2half(v[7] * inv));
    P4[tid] = o0;
    P4[256 + tid] = o1;
}

// ======================= BatchNorm =======================
__global__ __launch_bounds__(256)
void bn_final_kernel(const float* __restrict__ psum, const float* __restrict__ psq,
                     float* __restrict__ mean, float* __restrict__ rstd)
{
    const int c = threadIdx.x;
    const float inv_n = 1.f / (float)(BB * LL);
    float mu = psum[c] * inv_n;
    mean[c] = mu;
    rstd[c] = rsqrtf(psq[c] * inv_n - mu * mu + EPS);
}

__global__ __launch_bounds__(256)
void bn_apply_kernel(const __half* __restrict__ wy_h, const float* __restrict__ x,
                     const float* __restrict__ gamma, const float* __restrict__ beta,
                     const float* __restrict__ mean, const float* __restrict__ rstd,
                     float* __restrict__ out)
{
    const size_t i4 = ((size_t)blockIdx.x * 256 + threadIdx.x) * 4;
    const int c = (int)((i4 >> 11) & (CC - 1));
    const float ga = gamma[c] * rstd[c];
    const float bb = beta[c] - ga * mean[c];
    uint2 w = *(const uint2*)(wy_h + i4);
    float4 xv = *(const float4*)(x + i4);
    __half2 w0 = *reinterpret_cast<__half2*>(&w.x);
    __half2 w1 = *reinterpret_cast<__half2*>(&w.y);
    float4 o;
    o.x = ga * __low2float(w0)  + bb + xv.x;
    o.y = ga * __high2float(w0) + bb + xv.y;
    o.z = ga * __low2float(w1)  + bb + xv.z;
    o.w = ga * __high2float(w1) + bb + xv.w;
    *(float4*)(out + i4) = o;
}

// ======================= launch =======================
extern "C" void kernel_launch(void* const* d_in, const int* in_sizes, int n_in,
                              void* d_out, int out_size)
{
    const float* x     = (const float*)d_in[0];
    const float* Wg    = (const float*)d_in[1];
    const float* bg    = (const float*)d_in[2];
    const float* Wt    = (const float*)d_in[3];
    const float* bt    = (const float*)d_in[4];
    const float* Wp    = (const float*)d_in[5];
    const float* bp    = (const float*)d_in[6];   // unused: row-constant under softmax
    const float* Ww    = (const float*)d_in[7];
    const float* bw    = (const float*)d_in[8];
    const float* gamma = (const float*)d_in[9];
    const float* beta  = (const float*)d_in[10];
    float* out = (float*)d_out;
    (void)bp;

    __half *xT_hi, *xT_lo, *Mt_hi, *Mt_lo, *Nt_hi, *Nt_lo, *kT_hi, *kT_lo, *e_hi, *P, *wy_h;
    float *qv, *rv, *f, *psum, *psq, *mean, *rstd;
    cudaGetSymbolAddress((void**)&xT_hi, d_xT_hi);
    cudaGetSymbolAddress((void**)&xT_lo, d_xT_lo);
    cudaGetSymbolAddress((void**)&Mt_hi, d_Mt_hi);
    cudaGetSymbolAddress((void**)&Mt_lo, d_Mt_lo);
    cudaGetSymbolAddress((void**)&Nt_hi, d_Nt_hi);
    cudaGetSymbolAddress((void**)&Nt_lo, d_Nt_lo);
    cudaGetSymbolAddress((void**)&qv,    d_qv);
    cudaGetSymbolAddress((void**)&rv,    d_rv);
    cudaGetSymbolAddress((void**)&kT_hi, d_kT_hi);
    cudaGetSymbolAddress((void**)&kT_lo, d_kT_lo);
    cudaGetSymbolAddress((void**)&e_hi,  d_e_hi);
    cudaGetSymbolAddress((void**)&f,     d_f);
    cudaGetSymbolAddress((void**)&P,     d_P);
    cudaGetSymbolAddress((void**)&wy_h,  d_wy_h);
    cudaGetSymbolAddress((void**)&psum,  d_psum);
    cudaGetSymbolAddress((void**)&psq,   d_psq);
    cudaGetSymbolAddress((void**)&mean,  d_mean);
    cudaGetSymbolAddress((void**)&rstd,  d_rstd);

    const int SM1 = 2 * 49152;
    const int SM0 = 3 * 32768;
    cudaFuncSetAttribute(g12_kernel, cudaFuncAttributeMaxDynamicSharedMemorySize, SM1);
    cudaFuncSetAttribute(g3_kernel,  cudaFuncAttributeMaxDynamicSharedMemorySize, SM1);
    cudaFuncSetAttribute(g4_kernel,  cudaFuncAttributeMaxDynamicSharedMemorySize, SM0);

    // Worker stream + events, created once on first (uncaptured) call.
    static cudaStream_t s1 = nullptr;
    static cudaEvent_t evA[4], evB;
    if (s1 == nullptr) {
        cudaStreamCreateWithFlags(&s1, cudaStreamNonBlocking);
        for (int i = 0; i < 4; i++)
            cudaEventCreateWithFlags(&evA[i], cudaEventDisableTiming);
        cudaEventCreateWithFlags(&evB, cudaEventDisableTiming);
    }

    // ---- prep ----
    {
        dim3 g1(LL / 32, CC / 32, BB), b1(32, 8);
        transpose_split_kernel<<<g1, b1>>>(x, xT_hi, xT_lo, CC, LL);
        dim3 gw(CC, 2);
        wprep_kernel<<<gw, CC>>>(Wt, bt, Wp, Wg, bg, Ww,
                                 Mt_hi, Mt_lo, qv, Nt_hi, Nt_lo, rv);
        bn_zero_kernel<<<1, CC>>>(psum, psq);
    }

    // ---- G1+G2 merged ----
    g12_kernel<<<1024, 256, SM1>>>(xT_hi, xT_lo, Mt_hi, Mt_lo, Nt_hi, Nt_lo,
                                   qv, rv, kT_hi, kT_lo, e_hi);

    // ---- pipelined G3 -> (softmax, G4) in groups of 4 batches ----
    for (int g = 0; g < 4; g++) {
        dim3 g3grid(LL / GBN, LL / GBM, 4);
        g3_kernel<<<g3grid, 256, SM1>>>(kT_hi, kT_lo, xT_hi, xT_lo, f, g * 4);
        cudaEventRecord(evA[g], 0);
        cudaStreamWaitEvent(s1, evA[g], 0);
        const size_t fo = (size_t)(g * 4) * LL * LL;
        softmax_kernel<<<4 * LL, 256, 0, s1>>>(f + fo, P + fo);
        dim3 g4grid(LL / GBN, CC / GBM, 4);
        g4_kernel<<<g4grid, 256, SM0, s1>>>(e_hi, P, bw, wy_h, psum, psq, g * 4);
    }
    cudaEventRecord(evB, s1);
    cudaStreamWaitEvent(0, evB, 0);

    // ---- BN ----
    bn_final_kernel<<<1, CC>>>(psum, psq, mean, rstd);
    bn_apply_kernel<<<(int)((size_t)BB * CC * LL / 1024), 256>>>(
        wy_h, x, gamma, beta, mean, rstd, out);
}

// round 17
// speedup vs baseline: 1.1536x; 1.1536x over previous
#include <cuda_runtime.h>
#include <cuda_fp16.h>
#include <math.h>
#include <stdint.h>

#define BB 16
#define CC 256
#define LL 2048
#define EPS 1e-5f

// ======================= helpers =======================
__device__ __forceinline__ uint32_t smem_to_u32(const void* p) {
    uint32_t a;
    asm("{ .reg .u64 t; cvta.to.shared.u64 t, %1; cvt.u32.u64 %0, t; }" : "=r"(a) : "l"(p));
    return a;
}
__device__ __forceinline__ void cp_async16(uint32_t s, const void* g) {
    asm volatile("cp.async.cg.shared.global [%0], [%1], 16;" :: "r"(s), "l"(g));
}
#define CP_COMMIT() asm volatile("cp.async.commit_group;" ::: "memory")
#define CP_WAIT(n)  asm volatile("cp.async.wait_group %0;" :: "n"(n) : "memory")

__device__ __forceinline__ void ldsm4(uint32_t* r, uint32_t a) {
    asm volatile("ldmatrix.sync.aligned.m8n8.x4.shared.b16 {%0,%1,%2,%3}, [%4];"
                 : "=r"(r[0]), "=r"(r[1]), "=r"(r[2]), "=r"(r[3]) : "r"(a));
}
__device__ __forceinline__ void mma16816(float* c, const uint32_t* a, uint32_t b0, uint32_t b1) {
    asm volatile("mma.sync.aligned.m16n8k16.row.col.f32.f16.f16.f32 "
                 "{%0,%1,%2,%3}, {%4,%5,%6,%7}, {%8,%9}, {%0,%1,%2,%3};"
                 : "+f"(c[0]), "+f"(c[1]), "+f"(c[2]), "+f"(c[3])
                 : "r"(a[0]), "r"(a[1]), "r"(a[2]), "r"(a[3]), "r"(b0), "r"(b1));
}
__device__ __forceinline__ uint32_t pack_h2(__half a, __half b) {
    __half2 t = __halves2half2(a, b);
    return *reinterpret_cast<uint32_t*>(&t);
}

// ======================= scratch =======================
#define NLC  ((size_t)BB * LL * CC)
#define NLLs ((size_t)BB * LL * LL)

__device__ __align__(256) __half d_xT_hi[NLC], d_xT_lo[NLC];       // x^T (B,L,C)
__device__ __align__(256) __half d_Mt_hi[CC * CC], d_Mt_lo[CC * CC]; // Wp^T Wt
__device__ __align__(256) __half d_Nt_hi[CC * CC], d_Nt_lo[CC * CC]; // Ww Wg
__device__ float d_qv[CC], d_rv[CC];                                // Wp^T bt ; Ww bg
__device__ __align__(256) __half d_kT_hi[NLC];                      // kappa^T (B,L,C) hi only
__device__ __align__(256) __half d_e_hi[NLC];                      // eta (B,C,L) hi only
__device__ __align__(256) float  d_f[NLLs];                        // logits (B,L,L)
__device__ __align__(256) __half d_P[NLLs];                        // softmax fp16
__device__ __align__(256) __half d_wy_h[NLC];                      // W_y fp16 (B,C,L)
__device__ float d_psum[CC], d_psq[CC];
__device__ float d_mean[CC], d_rstd[CC];

// ======================= prep kernels =======================
__global__ __launch_bounds__(256)
void transpose_split_kernel(const float* __restrict__ src,
                            __half* __restrict__ dhi, __half* __restrict__ dlo,
                            int R, int S)
{
    __shared__ float tile[32][33];
    const size_t bo = (size_t)R * S * blockIdx.z;
    const int s0 = blockIdx.x * 32, r0 = blockIdx.y * 32;
    const int tx = threadIdx.x, ty = threadIdx.y;
#pragma unroll
    for (int k = 0; k < 4; k++)
        tile[ty + 8 * k][tx] = src[bo + (size_t)(r0 + ty + 8 * k) * S + s0 + tx];
    __syncthreads();
#pragma unroll
    for (int k = 0; k < 4; k++) {
        float v = tile[tx][ty + 8 * k];
        __half h = __float2half(v);
        size_t di = bo + (size_t)(s0 + ty + 8 * k) * R + r0 + tx;
        dhi[di] = h;
        dlo[di] = __float2half(v - __half2float(h));
    }
}

__global__ __launch_bounds__(256)
void wprep_kernel(const float* __restrict__ Wt, const float* __restrict__ bt,
                  const float* __restrict__ Wp,
                  const float* __restrict__ Wg, const float* __restrict__ bg,
                  const float* __restrict__ Ww,
                  __half* __restrict__ Mhi, __half* __restrict__ Mlo, float* __restrict__ qv,
                  __half* __restrict__ Nhi, __half* __restrict__ Nlo, float* __restrict__ rv)
{
    const int c = blockIdx.x, k = threadIdx.x;
    if (blockIdx.y == 0) {
        float acc = 0.f;
        for (int j = 0; j < CC; j++) acc += Wp[j * CC + c] * Wt[j * CC + k];
        __half h = __float2half(acc);
        Mhi[c * CC + k] = h;
        Mlo[c * CC + k] = __float2half(acc - __half2float(h));
        if (k == 0) {
            float q = 0.f;
            for (int j = 0; j < CC; j++) q += Wp[j * CC + c] * bt[j];
            qv[c] = q;
        }
    } else {
        float acc = 0.f;
        for (int j = 0; j < CC; j++) acc += Ww[c * CC + j] * Wg[j * CC + k];
        __half h = __float2half(acc);
        Nhi[c * CC + k] = h;
        Nlo[c * CC + k] = __float2half(acc - __half2float(h));
        if (k == 0) {
            float r = 0.f;
            for (int j = 0; j < CC; j++) r += Ww[c * CC + j] * bg[j];
            rv[c] = r;
        }
    }
}

__global__ void bn_zero_kernel(float* __restrict__ psum, float* __restrict__ psq)
{
    psum[threadIdx.x] = 0.f;
    psq[threadIdx.x]  = 0.f;
}

// ======================= merged split-fp16 mma.sync GEMM body =======================
// 256-thread CTA, 8 warps (2x4), warp tile 64x32, CTA tile 128x128. 2 CTAs/SM.
// MODE 2 (2-stage): KC "hi" chunks {Ahi,Bhi,Blo}: acc += Ahi*Bhi + Ahi*Blo.  (2-pass)
// MODE 0 (3-stage): KC chunks, Ahi*Bhi only.  (1-pass)
// EPI: 0 = fp32 out, 2 = fp16 hi out.
// BNRED: 0 none, 2 per-row stats.
#define GBM 128
#define GBN 128
#define GBK 64

template<int MODE, int BNRED>
__device__ __forceinline__ void gemm_body(
    const __half* __restrict__ Ahi,
    const __half* __restrict__ Bhi, const __half* __restrict__ Blo,
    const float* __restrict__ bias, int BIASROW, int EPI,
    float* __restrict__ Cf, __half* __restrict__ Chi,
    float* __restrict__ gpsum, float* __restrict__ gpsq,
    int K, int lda, int ldb, int ldc,
    int mBase, int nBase, size_t aoff, size_t boff, size_t coff,
    char* smem)
{
    constexpr uint32_t STG  = MODE ? 49152u : 32768u;
    constexpr int      NSTG = MODE ? 2 : 3;
    const uint32_t sbase = smem_to_u32(smem);

    const int tid  = threadIdx.x;
    const int lane = tid & 31;
    const int wid  = tid >> 5;
    const int wm   = wid >> 2;
    const int wn   = wid & 3;

    const int KC = K / GBK;
    const int NCH = KC;

    float acc[4][4][4];
#pragma unroll
    for (int i = 0; i < 4; i++)
#pragma unroll
        for (int j = 0; j < 4; j++)
#pragma unroll
            for (int q = 0; q < 4; q++) acc[i][j][q] = 0.f;

    auto issue_chunk = [&](int ch) {
        const int koff = ch * GBK;
        const uint32_t Ab = sbase + (uint32_t)(ch % NSTG) * STG;
        const uint32_t B0 = Ab + 16384;
#pragma unroll
        for (int i = 0; i < 4; i++) {
            int idx = tid + i * 256;
            int r = idx >> 3, c = idx & 7;
            uint32_t d = Ab + r * 128 + ((c ^ (r & 7)) << 4);
            cp_async16(d, Ahi + aoff + (size_t)(mBase + r) * lda + koff + c * 8);
        }
#pragma unroll
        for (int i = 0; i < 4; i++) {
            int idx = tid + i * 256;
            int r = idx >> 3, c = idx & 7;
            uint32_t d = B0 + r * 128 + ((c ^ (r & 7)) << 4);
            cp_async16(d, Bhi + boff + (size_t)(nBase + r) * ldb + koff + c * 8);
        }
        if (MODE) {
            const uint32_t B1 = Ab + 32768;
#pragma unroll
            for (int i = 0; i < 4; i++) {
                int idx = tid + i * 256;
                int r = idx >> 3, c = idx & 7;
                uint32_t d = B1 + r * 128 + ((c ^ (r & 7)) << 4);
                cp_async16(d, Blo + boff + (size_t)(nBase + r) * ldb + koff + c * 8);
            }
        }
    };

    issue_chunk(0); CP_COMMIT();
    if (MODE == 0 && NCH > 1) { issue_chunk(1); CP_COMMIT(); }

    const int laA = lane & 15;
    const int lcA = lane >> 4;
    const int lrB = ((lane >> 4) << 3) + (lane & 7);
    const int lcB = (lane >> 3) & 1;

    for (int ch = 0; ch < NCH; ch++) {
        if (MODE == 0) {
            if (ch + 1 < NCH) { CP_WAIT(1); } else { CP_WAIT(0); }
        } else {
            CP_WAIT(0);
        }
        __syncthreads();
        {
            const int next = (MODE == 0) ? ch + 2 : ch + 1;
            if (next < NCH) { issue_chunk(next); CP_COMMIT(); }
        }

        const uint32_t Ab = sbase + (uint32_t)(ch % NSTG) * STG;
        const uint32_t B0 = Ab + 16384;
        const uint32_t B1 = Ab + 32768;

#pragma unroll
        for (int ks = 0; ks < 4; ks++) {
            uint32_t afr[4][4], bh[2][4], bl[2][4];
#pragma unroll
            for (int i = 0; i < 4; i++) {
                int row = wm * 64 + i * 16 + laA;
                int chk = ks * 2 + lcA;
                ldsm4(afr[i], Ab + row * 128 + ((chk ^ (row & 7)) << 4));
            }
#pragma unroll
            for (int j = 0; j < 2; j++) {
                int row = wn * 32 + j * 16 + lrB;
                int chk = ks * 2 + lcB;
                ldsm4(bh[j], B0 + row * 128 + ((chk ^ (row & 7)) << 4));
            }
            if (MODE) {
#pragma unroll
                for (int j = 0; j < 2; j++) {
                    int row = wn * 32 + j * 16 + lrB;
                    int chk = ks * 2 + lcB;
                    ldsm4(bl[j], B1 + row * 128 + ((chk ^ (row & 7)) << 4));
                }
            }
#pragma unroll
            for (int i = 0; i < 4; i++)
#pragma unroll
                for (int j = 0; j < 4; j++)
                    mma16816(acc[i][j], afr[i], bh[j >> 1][(j & 1) * 2],
                             bh[j >> 1][(j & 1) * 2 + 1]);
            if (MODE) {
#pragma unroll
                for (int i = 0; i < 4; i++)
#pragma unroll
                    for (int j = 0; j < 4; j++)
                        mma16816(acc[i][j], afr[i], bl[j >> 1][(j & 1) * 2],
                                 bl[j >> 1][(j & 1) * 2 + 1]);
            }
        }
    }

    // ---- epilogue ----
    float* bnS = (float*)smem;
    float* bnQ = (float*)smem + 128;
    if (BNRED) {
        __syncthreads();
        if (tid < 128) { bnS[tid] = 0.f; bnQ[tid] = 0.f; }
        __syncthreads();
    }
    float lsum[8], lsq[8];
    if (BNRED) {
#pragma unroll
        for (int t = 0; t < 8; t++) { lsum[t] = 0.f; lsq[t] = 0.f; }
    }

    const int g  = lane >> 2;
    const int tg = lane & 3;
#pragma unroll
    for (int i = 0; i < 4; i++) {
        const int rm0 = mBase + wm * 64 + i * 16 + g;
        const int rm1 = rm0 + 8;
        float rb0 = 0.f, rb1 = 0.f;
        if (BIASROW && bias) { rb0 = bias[rm0]; rb1 = bias[rm1]; }
#pragma unroll
        for (int j = 0; j < 4; j++) {
            const int cn = nBase + wn * 32 + j * 8 + tg * 2;
            float c0 = acc[i][j][0], c1 = acc[i][j][1];
            float c2 = acc[i][j][2], c3 = acc[i][j][3];
            if (bias) {
                if (BIASROW) { c0 += rb0; c1 += rb0; c2 += rb1; c3 += rb1; }
                else {
                    float b0 = bias[cn], b1 = bias[cn + 1];
                    c0 += b0; c1 += b1; c2 += b0; c3 += b1;
                }
            }
            if (BNRED == 2) {
                lsum[i * 2]     += c0 + c1;
                lsq [i * 2]     += c0 * c0 + c1 * c1;
                lsum[i * 2 + 1] += c2 + c3;
                lsq [i * 2 + 1] += c2 * c2 + c3 * c3;
            }
            const size_t o0 = coff + (size_t)rm0 * ldc + cn;
            const size_t o1 = coff + (size_t)rm1 * ldc + cn;
            if (EPI == 0) {
                *(float2*)(Cf + o0) = make_float2(c0, c1);
                *(float2*)(Cf + o1) = make_float2(c2, c3);
            } else {
                *(uint32_t*)(Chi + o0) = pack_h2(__float2half(c0), __float2half(c1));
                *(uint32_t*)(Chi + o1) = pack_h2(__float2half(c2), __float2half(c3));
            }
        }
    }

    if (BNRED == 2) {
#pragma unroll
        for (int i = 0; i < 4; i++) {
#pragma unroll
            for (int h = 0; h < 2; h++) {
                int lr = wm * 64 + i * 16 + h * 8 + g;
                atomicAdd(&bnS[lr], lsum[i * 2 + h]);
                atomicAdd(&bnQ[lr], lsq[i * 2 + h]);
            }
        }
        __syncthreads();
        if (tid < 128) {
            atomicAdd(&gpsum[mBase + tid], bnS[tid]);
            atomicAdd(&gpsq[mBase + tid],  bnQ[tid]);
        }
    }
}

// ---- merged G1+G2 launch: 1024 CTAs, both MODE2 ----
__global__ __launch_bounds__(256, 2)
void g12_kernel(const __half* __restrict__ xT_hi, const __half* __restrict__ xT_lo,
                const __half* __restrict__ Mt_hi, const __half* __restrict__ Mt_lo,
                const __half* __restrict__ Nt_hi,
                const float* __restrict__ qv, const float* __restrict__ rv,
                __half* __restrict__ kT_hi, __half* __restrict__ e_hi)
{
    extern __shared__ char smem[];
    const size_t sLC = (size_t)LL * CC;
    const int id = blockIdx.x;
    if (id < 512) {
        // G1: kappaT[l,c] = sum_k x_hi[l,k]*(Mt_hi+Mt_lo)[c,k] + qv[c]  (hi out)
        const int bx = id & 1, by = (id >> 1) & 15, bz = id >> 5;
        gemm_body<2, 0>(xT_hi, Mt_hi, Mt_lo, qv, /*BIASROW=*/0, /*EPI=*/2,
                        nullptr, kT_hi, nullptr, nullptr,
                        CC, CC, CC, CC,
                        by * GBM, bx * GBN, (size_t)bz * sLC, 0, (size_t)bz * sLC,
                        smem);
    } else {
        // G2: eta[c,l] = sum_k Nt_hi[c,k]*(x_hi+x_lo)[l,k] + rv[c]  (hi out)
        const int id2 = id - 512;
        const int bx = id2 & 15, by = (id2 >> 4) & 1, bz = id2 >> 5;
        gemm_body<2, 0>(Nt_hi, xT_hi, xT_lo, rv, /*BIASROW=*/1, /*EPI=*/2,
                        nullptr, e_hi, nullptr, nullptr,
                        CC, CC, CC, LL,
                        by * GBM, bx * GBN, 0, (size_t)bz * sLC, (size_t)bz * sLC,
                        smem);
    }
}

// ---- G3 (2-pass): f[l,m] = sum_c kT_hi[l,c]*(x_hi+x_lo)[m,c] ----
__global__ __launch_bounds__(256, 2)
void g3_kernel(const __half* __restrict__ kT_hi,
               const __half* __restrict__ xT_hi, const __half* __restrict__ xT_lo,
               float* __restrict__ f)
{
    extern __shared__ char smem[];
    const size_t sLC = (size_t)LL * CC;
    const size_t sLL = (size_t)LL * LL;
    gemm_body<2, 0>(kT_hi, xT_hi, xT_lo, nullptr, 0, /*EPI=*/0,
                    f, nullptr, nullptr, nullptr,
                    CC, CC, CC, LL,
                    blockIdx.y * GBM, blockIdx.x * GBN,
                    (size_t)blockIdx.z * sLC, (size_t)blockIdx.z * sLC,
                    (size_t)blockIdx.z * sLL, smem);
}

// ---- G4: wy_h[c,l] = fp16( sum_m e_hi[c,m] P[l,m] + bw[c] ), per-channel stats ----
__global__ __launch_bounds__(256, 2)
void g4_kernel(const __half* __restrict__ e_hi, const __half* __restrict__ P,
               const float* __restrict__ bw, __half* __restrict__ wy_h,
               float* __restrict__ psum, float* __restrict__ psq)
{
    extern __shared__ char smem[];
    const size_t sLC = (size_t)LL * CC;
    const size_t sLL = (size_t)LL * LL;
    gemm_body<0, 2>(e_hi, P, nullptr, bw, /*BIASROW=*/1, /*EPI=*/2,
                    nullptr, wy_h, psum, psq,
                    LL, LL, LL, LL,
                    blockIdx.y * GBM, blockIdx.x * GBN,
                    (size_t)blockIdx.z * sLC, (size_t)blockIdx.z * sLL,
                    (size_t)blockIdx.z * sLC, smem);
}

// ======================= softmax: fp32 logits -> fp16 P =======================
__global__ __launch_bounds__(256)
void softmax_kernel(const float* __restrict__ f, __half* __restrict__ P)
{
    __shared__ float red[8];
    const float4* F4 = (const float4*)(f + (size_t)blockIdx.x * LL);
    uint2* P4 = (uint2*)(P + (size_t)blockIdx.x * LL);
    const int tid = threadIdx.x;

    float4 q0 = F4[tid], q1 = F4[256 + tid];
    float v[8] = {q0.x, q0.y, q0.z, q0.w, q1.x, q1.y, q1.z, q1.w};
    float m = -INFINITY;
#pragma unroll
    for (int j = 0; j < 8; j++) m = fmaxf(m, v[j]);
#pragma unroll
    for (int o = 16; o; o >>= 1) m = fmaxf(m, __shfl_xor_sync(0xffffffffu, m, o));
    if ((tid & 31) == 0) red[tid >> 5] = m;
    __syncthreads();
    float bm = red[0];
#pragma unroll
    for (int w = 1; w < 8; w++) bm = fmaxf(bm, red[w]);
    float s = 0.f;
#pragma unroll
    for (int j = 0; j < 8; j++) { v[j] = __expf(v[j] - bm); s += v[j]; }
#pragma unroll
    for (int o = 16; o; o >>= 1) s += __shfl_xor_sync(0xffffffffu, s, o);
    __syncthreads();
    if ((tid & 31) == 0) red[tid >> 5] = s;
    __syncthreads();
    float bs = 0.f;
#pragma unroll
    for (int w = 0; w < 8; w++) bs += red[w];
    const float inv = 1.f / bs;
    uint2 o0, o1;
    o0.x = pack_h2(__float2half(v[0] * inv), __float2half(v[1] * inv));
    o0.y = pack_h2(__float2half(v[2] * inv), __float2half(v[3] * inv));
    o1.x = pack_h2(__float2half(v[4] * inv), __float2half(v[5] * inv));
    o1.y = pack_h2(__float2half(v[6] * inv), __float2half(v[7] * inv));
    P4[tid] = o0;
    P4[256 + tid] = o1;
}

// ======================= BatchNorm =======================
__global__ __launch_bounds__(256)
void bn_final_kernel(const float* __restrict__ psum, const float* __restrict__ psq,
                     float* __restrict__ mean, float* __restrict__ rstd)
{
    const int c = threadIdx.x;
    const float inv_n = 1.f / (float)(BB * LL);
    float mu = psum[c] * inv_n;
    mean[c] = mu;
    rstd[c] = rsqrtf(psq[c] * inv_n - mu * mu + EPS);
}

__global__ __launch_bounds__(256)
void bn_apply_kernel(const __half* __restrict__ wy_h, const float* __restrict__ x,
                     const float* __restrict__ gamma, const float* __restrict__ beta,
                     const float* __restrict__ mean, const float* __restrict__ rstd,
                     float* __restrict__ out)
{
    const size_t i4 = ((size_t)blockIdx.x * 256 + threadIdx.x) * 4;
    const int c = (int)((i4 >> 11) & (CC - 1));
    const float ga = gamma[c] * rstd[c];
    const float bb = beta[c] - ga * mean[c];
    uint2 w = *(const uint2*)(wy_h + i4);
    float4 xv = *(const float4*)(x + i4);
    __half2 w0 = *reinterpret_cast<__half2*>(&w.x);
    __half2 w1 = *reinterpret_cast<__half2*>(&w.y);
    float4 o;
    o.x = ga * __low2float(w0)  + bb + xv.x;
    o.y = ga * __high2float(w0) + bb + xv.y;
    o.z = ga * __low2float(w1)  + bb + xv.z;
    o.w = ga * __high2float(w1) + bb + xv.w;
    *(float4*)(out + i4) = o;
}

// ======================= launch =======================
extern "C" void kernel_launch(void* const* d_in, const int* in_sizes, int n_in,
                              void* d_out, int out_size)
{
    const float* x     = (const float*)d_in[0];
    const float* Wg    = (const float*)d_in[1];
    const float* bg    = (const float*)d_in[2];
    const float* Wt    = (const float*)d_in[3];
    const float* bt    = (const float*)d_in[4];
    const float* Wp    = (const float*)d_in[5];
    const float* bp    = (const float*)d_in[6];   // unused: row-constant under softmax
    const float* Ww    = (const float*)d_in[7];
    const float* bw    = (const float*)d_in[8];
    const float* gamma = (const float*)d_in[9];
    const float* beta  = (const float*)d_in[10];
    float* out = (float*)d_out;
    (void)bp;

    __half *xT_hi, *xT_lo, *Mt_hi, *Mt_lo, *Nt_hi, *Nt_lo, *kT_hi, *e_hi, *P, *wy_h;
    float *qv, *rv, *f, *psum, *psq, *mean, *rstd;
    cudaGetSymbolAddress((void**)&xT_hi, d_xT_hi);
    cudaGetSymbolAddress((void**)&xT_lo, d_xT_lo);
    cudaGetSymbolAddress((void**)&Mt_hi, d_Mt_hi);
    cudaGetSymbolAddress((void**)&Mt_lo, d_Mt_lo);
    cudaGetSymbolAddress((void**)&Nt_hi, d_Nt_hi);
    cudaGetSymbolAddress((void**)&Nt_lo, d_Nt_lo);
    cudaGetSymbolAddress((void**)&qv,    d_qv);
    cudaGetSymbolAddress((void**)&rv,    d_rv);
    cudaGetSymbolAddress((void**)&kT_hi, d_kT_hi);
    cudaGetSymbolAddress((void**)&e_hi,  d_e_hi);
    cudaGetSymbolAddress((void**)&f,     d_f);
    cudaGetSymbolAddress((void**)&P,     d_P);
    cudaGetSymbolAddress((void**)&wy_h,  d_wy_h);
    cudaGetSymbolAddress((void**)&psum,  d_psum);
    cudaGetSymbolAddress((void**)&psq,   d_psq);
    cudaGetSymbolAddress((void**)&mean,  d_mean);
    cudaGetSymbolAddress((void**)&rstd,  d_rstd);

    const int SM1 = 2 * 49152;   // MODE 2: 2 stages x {A,Bhi,Blo} = 96 KB
    const int SM0 = 3 * 32768;   // MODE 0: 3 stages x {A,Bhi}     = 96 KB
    cudaFuncSetAttribute(g12_kernel, cudaFuncAttributeMaxDynamicSharedMemorySize, SM1);
    cudaFuncSetAttribute(g3_kernel,  cudaFuncAttributeMaxDynamicSharedMemorySize, SM1);
    cudaFuncSetAttribute(g4_kernel,  cudaFuncAttributeMaxDynamicSharedMemorySize, SM0);

    // ---- prep: xT split; folded weight products; zero BN accumulators ----
    {
        dim3 g1(LL / 32, CC / 32, BB), b1(32, 8);
        transpose_split_kernel<<<g1, b1>>>(x, xT_hi, xT_lo, CC, LL);
        dim3 gw(CC, 2);
        wprep_kernel<<<gw, CC>>>(Wt, bt, Wp, Wg, bg, Ww,
                                 Mt_hi, Mt_lo, qv, Nt_hi, Nt_lo, rv);
        bn_zero_kernel<<<1, CC>>>(psum, psq);
    }

    // ---- G1+G2 merged (1024 CTAs, both 2-pass) ----
    g12_kernel<<<1024, 256, SM1>>>(xT_hi, xT_lo, Mt_hi, Mt_lo, Nt_hi,
                                   qv, rv, kT_hi, e_hi);

    // ---- G3 (2-pass): logits ----
    {
        dim3 grid(LL / GBN, LL / GBM, BB);
        g3_kernel<<<grid, 256, SM1>>>(kT_hi, xT_hi, xT_lo, f);
    }
    // ---- softmax -> P fp16 ----
    softmax_kernel<<<BB * LL, 256>>>(f, P);

    // ---- G4: wy (B,C,L) fp16 + fused per-channel BN stats ----
    {
        dim3 grid(LL / GBN, CC / GBM, BB);
        g4_kernel<<<grid, 256, SM0>>>(e_hi, P, bw, wy_h, psum, psq);
    }

    // ---- BN ----
    bn_final_kernel<<<1, CC>>>(psum, psq, mean, rstd);
    bn_apply_kernel<<<(int)((size_t)BB * CC * LL / 1024), 256>>>(
        wy_h, x, gamma, beta, mean, rstd, out);
}